// round 10
// baseline (speedup 1.0000x reference)
#include <cuda_runtime.h>
#include <cuda_bf16.h>
#include <cstdint>

#define DIMD 256
#define NEMB 512
#define TM   128
#define NCHUNK 64
#define MARGIN 0.25f
#define CAND_CAP 16

__device__ __align__(16) float          g_EN [NEMB * DIMD];  // normalized codebook f32 [j][k]
__device__ __align__(16) float          g_C  [NEMB];         // c_j
__device__ __align__(16) unsigned short g_Bbf[NEMB * DIMD];  // bf16 codebook [j][k]
__device__ double g_entropy;
__device__ double g_partials[2048];

// ---- smem layout (byte offsets), total 113152 -> 2 CTA/SM ----
#define A_STRIDE  528u              // 264 halves: bank stride 4 -> ldmatrix conflict-free
#define A_OFF     0u                // 128 * 528 = 67584
#define B_OFF     67584u            // single buffer: 64 * 528 = 33792
#define SC_OFF    101376u           // 512 f  -> 103424
#define SSQ_OFF   103424u           // 128 f  -> 103936
#define SIND_OFF  103936u           // 128 i  -> 104448
#define CCNT_OFF  104448u           // 128 i  -> 104960
#define CLIST_OFF 104960u           // 128*16 i = 8192 -> 113152
#define DRED_OFF  104960u           // 256 d = 2048 (overlaps cList; disjoint live ranges)
#define SMEM_REQ  113152u

#define CP16(dst, src) asm volatile("cp.async.cg.shared.global [%0], [%1], 16;" :: "r"(dst), "l"(src))
#define CP_COMMIT()    asm volatile("cp.async.commit_group;")
#define CP_WAIT(n)     asm volatile("cp.async.wait_group %0;" :: "n"(n))

#define LDM_X4(r0, r1, r2, r3, a) \
    asm volatile("ldmatrix.sync.aligned.m8n8.x4.shared.b16 {%0,%1,%2,%3}, [%4];" \
                 : "=r"(r0), "=r"(r1), "=r"(r2), "=r"(r3) : "r"(a))

#define MMA_BF16(c, a0, a1, a2, a3, b0, b1) \
    asm volatile("mma.sync.aligned.m16n8k16.row.col.f32.bf16.bf16.f32 " \
                 "{%0,%1,%2,%3}, {%4,%5,%6,%7}, {%8,%9}, {%0,%1,%2,%3};" \
                 : "+f"((c)[0]), "+f"((c)[1]), "+f"((c)[2]), "+f"((c)[3]) \
                 : "r"(a0), "r"(a1), "r"(a2), "r"(a3), "r"(b0), "r"(b1))

__device__ __forceinline__ uint32_t bf16x2_of(float lo, float hi) {
    uint32_t r;
    asm("cvt.rn.bf16x2.f32 %0, %1, %2;" : "=r"(r) : "f"(hi), "f"(lo));  // %2 -> low half
    return r;
}
__device__ __forceinline__ float gridscore(float sqr, float dot, float cj) {
    return __fadd_rn(__fsub_rn(sqr, __fmul_rn(2.0f, dot)), cj);
}

// ---------------- Phase A1: normalize codebook rows (proven) ----------------
__global__ void k_norm(const float* __restrict__ emb) {
    int j = blockIdx.x, t = threadIdx.x;  // 512 x 64
    __shared__ float red[64];
    float4 v = reinterpret_cast<const float4*>(emb + j * DIMD)[t];
    red[t] = v.x * v.x + v.y * v.y + v.z * v.z + v.w * v.w;
    __syncthreads();
    for (int o = 32; o > 0; o >>= 1) { if (t < o) red[t] += red[t + o]; __syncthreads(); }
    float nrm = sqrtf(red[0]);
    __syncthreads();
    float4 q;
    q.x = v.x / nrm; q.y = v.y / nrm; q.z = v.z / nrm; q.w = v.w / nrm;
    reinterpret_cast<float4*>(g_EN + j * DIMD)[t] = q;
    red[t] = q.x * q.x + q.y * q.y + q.z * q.z + q.w * q.w;
    __syncthreads();
    for (int o = 32; o > 0; o >>= 1) { if (t < o) red[t] += red[t + o]; __syncthreads(); }
    if (t == 0) g_C[j] = red[0];
}

// ---------------- Phase A2: entropy (proven) ----------------
__global__ void k_entropy() {
    int t = threadIdx.x;  // 256
    float s = 0.f;
    for (int j = 0; j < NEMB; j++) s += g_EN[j * DIMD + t];
    double val = 2.0 * (double)NEMB * ((double)g_C[t] + (double)g_C[t + 256])
               - 2.0 * (double)s * (double)s;
    __shared__ double red[256];
    red[t] = val; __syncthreads();
    for (int o = 128; o > 0; o >>= 1) { if (t < o) red[t] += red[t + o]; __syncthreads(); }
    if (t == 0) g_entropy = red[0];
}

// ---------------- Phase A3: bf16 codebook ----------------
__global__ void k_prepB() {
    int idx = blockIdx.x * 256 + threadIdx.x;   // 131072
    float x = g_EN[idx];
    unsigned short h;
    asm("cvt.rn.bf16.f32 %0, %1;" : "=h"(h) : "f"(x));
    g_Bbf[idx] = h;
}

// exact rescore: serial ascending-k fmaf chain == R2's passing arithmetic
__device__ __forceinline__ float rescore(const float* __restrict__ input, long grow,
                                         int j, float cj, float sqr) {
    const float4* xp = reinterpret_cast<const float4*>(input + grow * DIMD);
    const float4* ep = reinterpret_cast<const float4*>(g_EN + j * DIMD);
    float d = 0.f;
#pragma unroll 8
    for (int k = 0; k < 64; k++) {
        float4 x = xp[k], e = ep[k];
        d = __fmaf_rn(x.x, e.x, d); d = __fmaf_rn(x.y, e.y, d);
        d = __fmaf_rn(x.z, e.z, d); d = __fmaf_rn(x.w, e.w, d);
    }
    return __fadd_rn(__fsub_rn(sqr, __fmul_rn(2.0f, d)), cj);
}

// ------- Main: bf16 mma.sync (32x32 warp tile) + filter + rescore, 2 CTA/SM --
__global__ void __launch_bounds__(256, 2) k_main(
        const float* __restrict__ input,
        float* __restrict__ out,
        float* __restrict__ ind_out)
{
    extern __shared__ char smraw[];
    uint32_t raw32 = (uint32_t)__cvta_generic_to_shared(smraw);
    float*  sc    = (float*)(smraw + SC_OFF);
    float*  sSq   = (float*)(smraw + SSQ_OFF);
    int*    sInd  = (int*)(smraw + SIND_OFF);
    int*    cCnt  = (int*)(smraw + CCNT_OFF);
    int*    cList = (int*)(smraw + CLIST_OFF);
    double* dred  = (double*)(smraw + DRED_OFF);

    const int  tid  = threadIdx.x;
    const int  wid  = tid >> 5, lane = tid & 31;
    const long r0   = (long)blockIdx.x * TM;
    const int  mg   = wid >> 1, ng = wid & 1;       // warp tile: rows mg*32.., cols ng*32..
    const int  tq   = lane >> 3, rr = lane & 7;

    if (tid < TM) cCnt[tid] = 0;
    for (int i = tid; i < NEMB; i += 256) sc[i] = g_C[i];

    // ---- A load: f32 -> bf16 into padded smem; exact double row norms (proven) ----
    {
        int r = tid >> 1, h = tid & 1;
        const float4* src = reinterpret_cast<const float4*>(input + (r0 + r) * DIMD + h * 128);
        uint32_t dst = raw32 + A_OFF + (uint32_t)r * A_STRIDE + (uint32_t)h * 256u;
        double dsq = 0.0;
#pragma unroll 8
        for (int q = 0; q < 32; q++) {
            float4 v = src[q];
            dsq += (double)v.x * v.x + (double)v.y * v.y + (double)v.z * v.z + (double)v.w * v.w;
            uint32_t p0 = bf16x2_of(v.x, v.y);
            uint32_t p1 = bf16x2_of(v.z, v.w);
            asm volatile("st.shared.v2.b32 [%0], {%1, %2};" :: "r"(dst + q * 8u), "r"(p0), "r"(p1));
        }
        dred[tid] = dsq;
    }
    // prefetch B chunk 0 (64 j-rows x 512B)
#pragma unroll
    for (int q = 0; q < 8; q++) {
        int idx = tid + q * 256;
        int row = idx >> 5, seg = idx & 31;
        CP16(raw32 + B_OFF + (uint32_t)row * A_STRIDE + (uint32_t)seg * 16u,
             (const char*)g_Bbf + (size_t)row * 512 + seg * 16);
    }
    CP_COMMIT();
    __syncthreads();
    if (tid < TM) sSq[tid] = (float)(dred[2 * tid] + dred[2 * tid + 1]);
    __syncthreads();   // sSq ready; dred region free for cList reuse

    // ---- fragment addresses (proven lane patterns) ----
    const uint32_t aB0 = raw32 + A_OFF
        + (uint32_t)(mg * 32 + ((tq & 1) << 3) + rr) * A_STRIDE
        + (uint32_t)((tq >> 1) << 4);
    const uint32_t aB1 = aB0 + 16u * A_STRIDE;
    const uint32_t bPart = (uint32_t)((ng * 32 + ((tq >> 1) << 3) + rr) * A_STRIDE
        + ((tq & 1) << 4));
    const uint32_t bBuf = raw32 + B_OFF + bPart;

    const int rb = mg * 32 + (lane >> 2);           // rows rb, rb+8, rb+16, rb+24
    const float sqr4[4] = { sSq[rb], sSq[rb + 8], sSq[rb + 16], sSq[rb + 24] };
    float bs[4] = { 3.0e38f, 3.0e38f, 3.0e38f, 3.0e38f };

    for (int ch = 0; ch < 8; ch++) {
        CP_WAIT(0);
        __syncthreads();                            // B chunk ready, all warps present

        float acc[8][4];
#pragma unroll
        for (int i = 0; i < 8; i++)
            acc[i][0] = acc[i][1] = acc[i][2] = acc[i][3] = 0.f;

#pragma unroll 2
        for (int kk = 0; kk < 16; kk++) {
            const uint32_t ko = (uint32_t)kk * 32u;
            uint32_t a0, a1, a2, a3, a4, a5, a6, a7;
            uint32_t b00, b01, b02, b03, b10, b11, b12, b13;
            LDM_X4(a0, a1, a2, a3, aB0 + ko);
            LDM_X4(a4, a5, a6, a7, aB1 + ko);
            LDM_X4(b00, b01, b02, b03, bBuf + ko);
            LDM_X4(b10, b11, b12, b13, bBuf + 16u * A_STRIDE + ko);
            MMA_BF16(acc[0], a0, a1, a2, a3, b00, b01);
            MMA_BF16(acc[1], a0, a1, a2, a3, b02, b03);
            MMA_BF16(acc[2], a0, a1, a2, a3, b10, b11);
            MMA_BF16(acc[3], a0, a1, a2, a3, b12, b13);
            MMA_BF16(acc[4], a4, a5, a6, a7, b00, b01);
            MMA_BF16(acc[5], a4, a5, a6, a7, b02, b03);
            MMA_BF16(acc[6], a4, a5, a6, a7, b10, b11);
            MMA_BF16(acc[7], a4, a5, a6, a7, b12, b13);
        }
        __syncthreads();                            // all warps done reading B buffer

        // refill buffer for next chunk NOW; overlaps with epilogue below
        if (ch < 7) {
#pragma unroll
            for (int q = 0; q < 8; q++) {
                int idx = tid + q * 256;
                int row = idx >> 5, seg = idx & 31;
                CP16(raw32 + B_OFF + (uint32_t)row * A_STRIDE + (uint32_t)seg * 16u,
                     (const char*)g_Bbf + (size_t)((ch + 1) * NCHUNK + row) * 512 + seg * 16);
            }
            CP_COMMIT();
        }

        // ---- epilogue sweep 1: fold into running per-row best ----
        const int jb = ch * NCHUNK + ng * 32 + 2 * (lane & 3);
#pragma unroll
        for (int m = 0; m < 2; m++) {
#pragma unroll
            for (int f = 0; f < 4; f++) {
                int j0 = jb + f * 8;
                const float* c = acc[m * 4 + f];
                float s00 = gridscore(sqr4[2 * m],     c[0], sc[j0]);
                float s01 = gridscore(sqr4[2 * m],     c[1], sc[j0 + 1]);
                float s10 = gridscore(sqr4[2 * m + 1], c[2], sc[j0]);
                float s11 = gridscore(sqr4[2 * m + 1], c[3], sc[j0 + 1]);
                bs[2 * m]     = fminf(bs[2 * m],     fminf(s00, s01));
                bs[2 * m + 1] = fminf(bs[2 * m + 1], fminf(s10, s11));
            }
        }
        float thr[4];
#pragma unroll
        for (int m = 0; m < 4; m++) {
            float q = bs[m];
            q = fminf(q, __shfl_xor_sync(0xFFFFFFFFu, q, 1));
            q = fminf(q, __shfl_xor_sync(0xFFFFFFFFu, q, 2));
            thr[m] = q + MARGIN;
        }

        // ---- epilogue sweep 2: push margin candidates ----
#pragma unroll
        for (int m = 0; m < 2; m++) {
#pragma unroll
            for (int f = 0; f < 4; f++) {
                int j0 = jb + f * 8;
                const float* c = acc[m * 4 + f];
                float s00 = gridscore(sqr4[2 * m],     c[0], sc[j0]);
                float s01 = gridscore(sqr4[2 * m],     c[1], sc[j0 + 1]);
                float s10 = gridscore(sqr4[2 * m + 1], c[2], sc[j0]);
                float s11 = gridscore(sqr4[2 * m + 1], c[3], sc[j0 + 1]);
                int rA = rb + m * 16, rB = rA + 8;
                if (s00 <= thr[2 * m])     { int p = atomicAdd(&cCnt[rA], 1); if (p < CAND_CAP) cList[rA * CAND_CAP + p] = j0; }
                if (s01 <= thr[2 * m])     { int p = atomicAdd(&cCnt[rA], 1); if (p < CAND_CAP) cList[rA * CAND_CAP + p] = j0 + 1; }
                if (s10 <= thr[2 * m + 1]) { int p = atomicAdd(&cCnt[rB], 1); if (p < CAND_CAP) cList[rB * CAND_CAP + p] = j0; }
                if (s11 <= thr[2 * m + 1]) { int p = atomicAdd(&cCnt[rB], 1); if (p < CAND_CAP) cList[rB * CAND_CAP + p] = j0 + 1; }
            }
        }
    }
    __syncthreads();   // candidate lists complete

    // ---- exact rescore of candidates (2 threads per row, proven) ----
    {
        int row = tid >> 1, h = tid & 1;
        int cnt = cCnt[row];
        float bsv = 3.0e38f; int bi = NEMB;
        if (cnt <= CAND_CAP) {
            for (int i = h; i < cnt; i += 2) {
                int j = cList[row * CAND_CAP + i];
                float s = rescore(input, r0 + row, j, sc[j], sSq[row]);
                if (s < bsv || (s == bsv && j < bi)) { bsv = s; bi = j; }
            }
        } else {  // overflow fallback: exact scan of all 512
            for (int j = h; j < NEMB; j += 2) {
                float s = rescore(input, r0 + row, j, sc[j], sSq[row]);
                if (s < bsv || (s == bsv && j < bi)) { bsv = s; bi = j; }
            }
        }
        float os = __shfl_xor_sync(0xFFFFFFFFu, bsv, 1);
        int   oi = __shfl_xor_sync(0xFFFFFFFFu, bi, 1);
        if (os < bsv || (os == bsv && oi < bi)) { bsv = os; bi = oi; }
        if (h == 0) {
            sInd[row] = bi;
            ind_out[r0 + row] = (float)bi;
        }
    }
    __syncthreads();   // sInd ready; cList dead -> dred region reusable

    // ---- gather -> out, diff accumulation (proven) ----
    {
        int r = tid >> 1, h = tid & 1;
        int jb2 = sInd[r];
        const float4* qp = reinterpret_cast<const float4*>(g_EN + jb2 * DIMD + h * 128);
        const float4* xp = reinterpret_cast<const float4*>(input + (r0 + r) * DIMD + h * 128);
        float4* op = reinterpret_cast<float4*>(out + (r0 + r) * DIMD + h * 128);
        float fsum = 0.f;
#pragma unroll 8
        for (int k = 0; k < 32; k++) {
            float4 q = qp[k], x = xp[k];
            op[k] = q;
            float dx = q.x - x.x, dy = q.y - x.y, dz = q.z - x.z, dw = q.w - x.w;
            fsum += dx * dx + dy * dy + dz * dz + dw * dw;
        }
        dred[tid] = (double)fsum;
    }
    __syncthreads();
    for (int o = 128; o > 0; o >>= 1) { if (tid < o) dred[tid] += dred[tid + o]; __syncthreads(); }
    if (tid == 0) g_partials[blockIdx.x] = dred[0];
}

// ---------------- final: loss = diff - entropy/E^2 ----------------
__global__ void k_final(float* __restrict__ loss_out, int nblocks, long n) {
    __shared__ double red[256];
    int t = threadIdx.x;
    double s = 0.0;
    for (int i = t; i < nblocks; i += 256) s += g_partials[i];
    red[t] = s; __syncthreads();
    for (int o = 128; o > 0; o >>= 1) { if (t < o) red[t] += red[t + o]; __syncthreads(); }
    if (t == 0) {
        double diff = red[0] / (double)n;
        loss_out[0] = (float)(diff - g_entropy / ((double)NEMB * (double)NEMB));
    }
}

extern "C" void kernel_launch(void* const* d_in, const int* in_sizes, int n_in,
                              void* d_out, int out_size) {
    const float* input = (const float*)d_in[0];
    const float* emb   = (const float*)d_in[1];
    long n     = (long)in_sizes[0];        // 33554432
    int  nrows = (int)(n / DIMD);          // 131072
    int  nblk  = nrows / TM;               // 1024
    float* out    = (float*)d_out;
    float* loss_p = out + n;               // layout: [out | loss | embed_ind]
    float* ind_p  = out + n + 1;

    cudaFuncSetAttribute(k_main, cudaFuncAttributeMaxDynamicSharedMemorySize, SMEM_REQ);
    k_norm   <<<NEMB, 64>>>(emb);
    k_entropy<<<1, 256>>>();
    k_prepB  <<<512, 256>>>();
    k_main   <<<nblk, 256, SMEM_REQ>>>(input, out, ind_p);
    k_final  <<<1, 256>>>(loss_p, nblk, n);
}

// round 11
// speedup vs baseline: 1.3692x; 1.3692x over previous
#include <cuda_runtime.h>
#include <cuda_bf16.h>
#include <cstdint>

#define DIMD 256
#define NEMB 512
#define TM   128
#define NTHREADS 512
#define MARGIN 0.25f
#define CAND_CAP 16

__device__ __align__(16) float          g_EN [NEMB * DIMD];  // normalized codebook f32 [j][k]
__device__ __align__(16) float          g_C  [NEMB];         // c_j
__device__ __align__(16) unsigned short g_Bbf[NEMB * DIMD];  // bf16 codebook [j][k]
__device__ double g_entropy;
__device__ double g_partials[2048];

// ---- smem layout (byte offsets) ----
#define A_STRIDE  528u              // 264 halves: bank stride 4 -> ldmatrix conflict-free
#define A_OFF     0u                // 128 * 528 = 67584
#define B_OFF     67584u            // 2 bufs x 67584 = 135168 -> 202752
#define B_BUFSZ   67584u
#define SC_OFF    202752u           // 512 f  -> 204800
#define SSQ_OFF   204800u           // 128 f  -> 205312
#define SIND_OFF  205312u           // 128 i  -> 205824
#define CCNT_OFF  205824u           // 128 i  -> 206336
#define CLIST_OFF 206336u           // 128*16 i = 8192 -> 214528
#define DRED_OFF  206336u           // 512 d = 4096 (overlaps cList; disjoint live ranges)
#define SMEM_REQ  214528u

#define CP16(dst, src) asm volatile("cp.async.cg.shared.global [%0], [%1], 16;" :: "r"(dst), "l"(src))
#define CP_COMMIT()    asm volatile("cp.async.commit_group;")
#define CP_WAIT(n)     asm volatile("cp.async.wait_group %0;" :: "n"(n))

#define LDM_X4(r0, r1, r2, r3, a) \
    asm volatile("ldmatrix.sync.aligned.m8n8.x4.shared.b16 {%0,%1,%2,%3}, [%4];" \
                 : "=r"(r0), "=r"(r1), "=r"(r2), "=r"(r3) : "r"(a))

#define MMA_BF16(c, a0, a1, a2, a3, b0, b1) \
    asm volatile("mma.sync.aligned.m16n8k16.row.col.f32.bf16.bf16.f32 " \
                 "{%0,%1,%2,%3}, {%4,%5,%6,%7}, {%8,%9}, {%0,%1,%2,%3};" \
                 : "+f"((c)[0]), "+f"((c)[1]), "+f"((c)[2]), "+f"((c)[3]) \
                 : "r"(a0), "r"(a1), "r"(a2), "r"(a3), "r"(b0), "r"(b1))

__device__ __forceinline__ uint32_t bf16x2_of(float lo, float hi) {
    uint32_t r;
    asm("cvt.rn.bf16x2.f32 %0, %1, %2;" : "=r"(r) : "f"(hi), "f"(lo));  // %2 -> low half
    return r;
}
__device__ __forceinline__ float gridscore(float sqr, float dot, float cj) {
    return __fadd_rn(__fsub_rn(sqr, __fmul_rn(2.0f, dot)), cj);
}

// ---------------- Phase A1: normalize codebook rows (proven) ----------------
__global__ void k_norm(const float* __restrict__ emb) {
    int j = blockIdx.x, t = threadIdx.x;  // 512 x 64
    __shared__ float red[64];
    float4 v = reinterpret_cast<const float4*>(emb + j * DIMD)[t];
    red[t] = v.x * v.x + v.y * v.y + v.z * v.z + v.w * v.w;
    __syncthreads();
    for (int o = 32; o > 0; o >>= 1) { if (t < o) red[t] += red[t + o]; __syncthreads(); }
    float nrm = sqrtf(red[0]);
    __syncthreads();
    float4 q;
    q.x = v.x / nrm; q.y = v.y / nrm; q.z = v.z / nrm; q.w = v.w / nrm;
    reinterpret_cast<float4*>(g_EN + j * DIMD)[t] = q;
    red[t] = q.x * q.x + q.y * q.y + q.z * q.z + q.w * q.w;
    __syncthreads();
    for (int o = 32; o > 0; o >>= 1) { if (t < o) red[t] += red[t + o]; __syncthreads(); }
    if (t == 0) g_C[j] = red[0];
}

// ---------------- Phase A2: entropy (proven) ----------------
__global__ void k_entropy() {
    int t = threadIdx.x;  // 256
    float s = 0.f;
    for (int j = 0; j < NEMB; j++) s += g_EN[j * DIMD + t];
    double val = 2.0 * (double)NEMB * ((double)g_C[t] + (double)g_C[t + 256])
               - 2.0 * (double)s * (double)s;
    __shared__ double red[256];
    red[t] = val; __syncthreads();
    for (int o = 128; o > 0; o >>= 1) { if (t < o) red[t] += red[t + o]; __syncthreads(); }
    if (t == 0) g_entropy = red[0];
}

// ---------------- Phase A3: bf16 codebook ----------------
__global__ void k_prepB() {
    int idx = blockIdx.x * 256 + threadIdx.x;   // 131072
    float x = g_EN[idx];
    unsigned short h;
    asm("cvt.rn.bf16.f32 %0, %1;" : "=h"(h) : "f"(x));
    g_Bbf[idx] = h;
}

// exact rescore: serial ascending-k fmaf chain == R2's passing arithmetic
__device__ __forceinline__ float rescore(const float* __restrict__ input, long grow,
                                         int j, float cj, float sqr) {
    const float4* xp = reinterpret_cast<const float4*>(input + grow * DIMD);
    const float4* ep = reinterpret_cast<const float4*>(g_EN + j * DIMD);
    float d = 0.f;
#pragma unroll 8
    for (int k = 0; k < 64; k++) {
        float4 x = xp[k], e = ep[k];
        d = __fmaf_rn(x.x, e.x, d); d = __fmaf_rn(x.y, e.y, d);
        d = __fmaf_rn(x.z, e.z, d); d = __fmaf_rn(x.w, e.w, d);
    }
    return __fadd_rn(__fsub_rn(sqr, __fmul_rn(2.0f, d)), cj);
}

// ------- Main: R7 structure, 512 threads (16 warps), warp tile 16x64 --------
__global__ void __launch_bounds__(NTHREADS, 1) k_main(
        const float* __restrict__ input,
        float* __restrict__ out,
        float* __restrict__ ind_out)
{
    extern __shared__ char smraw[];
    uint32_t raw32 = (uint32_t)__cvta_generic_to_shared(smraw);
    float*  sc    = (float*)(smraw + SC_OFF);
    float*  sSq   = (float*)(smraw + SSQ_OFF);
    int*    sInd  = (int*)(smraw + SIND_OFF);
    int*    cCnt  = (int*)(smraw + CCNT_OFF);
    int*    cList = (int*)(smraw + CLIST_OFF);
    double* dred  = (double*)(smraw + DRED_OFF);

    const int  tid  = threadIdx.x;
    const int  wid  = tid >> 5, lane = tid & 31;
    const long r0   = (long)blockIdx.x * TM;
    const int  mg   = wid >> 1, ng = wid & 1;       // warp tile: rows mg*16.., cols ng*64..
    const int  tq   = lane >> 3, rr = lane & 7;

    if (tid < TM) cCnt[tid] = 0;
    for (int i = tid; i < NEMB; i += NTHREADS) sc[i] = g_C[i];

    // ---- A load: f32 -> bf16 into padded smem; exact double row norms ----
    {
        int r = tid >> 2, h = tid & 3;              // 4 threads per row, 64 floats each
        const float4* src = reinterpret_cast<const float4*>(input + (r0 + r) * DIMD + h * 64);
        uint32_t dst = raw32 + A_OFF + (uint32_t)r * A_STRIDE + (uint32_t)h * 128u;
        double dsq = 0.0;
#pragma unroll 8
        for (int q = 0; q < 16; q++) {
            float4 v = src[q];
            dsq += (double)v.x * v.x + (double)v.y * v.y + (double)v.z * v.z + (double)v.w * v.w;
            uint32_t p0 = bf16x2_of(v.x, v.y);
            uint32_t p1 = bf16x2_of(v.z, v.w);
            asm volatile("st.shared.v2.b32 [%0], {%1, %2};" :: "r"(dst + q * 8u), "r"(p0), "r"(p1));
        }
        dred[tid] = dsq;
    }
    // prefetch B chunk 0 (128 j-rows x 512B)
#pragma unroll
    for (int q = 0; q < 8; q++) {
        int idx = tid + q * NTHREADS;
        int row = idx >> 5, seg = idx & 31;
        CP16(raw32 + B_OFF + (uint32_t)row * A_STRIDE + (uint32_t)seg * 16u,
             (const char*)g_Bbf + (size_t)row * 512 + seg * 16);
    }
    CP_COMMIT();
    __syncthreads();
    if (tid < TM) sSq[tid] = (float)(dred[4 * tid] + dred[4 * tid + 1]
                                   + dred[4 * tid + 2] + dred[4 * tid + 3]);
    __syncthreads();   // sSq ready; dred region free for cList use

    // ---- fragment addresses (proven lane patterns) ----
    const uint32_t aB = raw32 + A_OFF
        + (uint32_t)(mg * 16 + ((tq & 1) << 3) + rr) * A_STRIDE
        + (uint32_t)((tq >> 1) << 4);
    const uint32_t bPart = (uint32_t)((ng * 64 + ((tq >> 1) << 3) + rr) * A_STRIDE
        + ((tq & 1) << 4));

    const int rb = mg * 16 + (lane >> 2);           // rows rb, rb+8
    const float sqr0 = sSq[rb], sqr1 = sSq[rb + 8];
    float bs0 = 3.0e38f, bs1 = 3.0e38f;

    for (int ch = 0; ch < 4; ch++) {
        if (ch < 3) {
#pragma unroll
            for (int q = 0; q < 8; q++) {
                int idx = tid + q * NTHREADS;
                int row = idx >> 5, seg = idx & 31;
                CP16(raw32 + B_OFF + (uint32_t)((ch + 1) & 1) * B_BUFSZ
                         + (uint32_t)row * A_STRIDE + (uint32_t)seg * 16u,
                     (const char*)g_Bbf + (size_t)((ch + 1) * 128 + row) * 512 + seg * 16);
            }
            CP_COMMIT();
            CP_WAIT(1);
        } else {
            CP_WAIT(0);
        }
        __syncthreads();

        const uint32_t bBuf = raw32 + B_OFF + (uint32_t)(ch & 1) * B_BUFSZ + bPart;
        float acc[8][4];
#pragma unroll
        for (int i = 0; i < 8; i++)
            acc[i][0] = acc[i][1] = acc[i][2] = acc[i][3] = 0.f;

#pragma unroll 2
        for (int kk = 0; kk < 16; kk++) {
            const uint32_t ko = (uint32_t)kk * 32u;
            uint32_t a0, a1, a2, a3;
            LDM_X4(a0, a1, a2, a3, aB + ko);
#pragma unroll
            for (int nq = 0; nq < 4; nq++) {
                uint32_t b0, b1, b2, b3;
                LDM_X4(b0, b1, b2, b3, bBuf + (uint32_t)nq * (16u * A_STRIDE) + ko);
                MMA_BF16(acc[2 * nq],     a0, a1, a2, a3, b0, b1);
                MMA_BF16(acc[2 * nq + 1], a0, a1, a2, a3, b2, b3);
            }
        }

        // ---- epilogue sweep 1: fold into running per-row best ----
        const int jb = ch * 128 + ng * 64 + 2 * (lane & 3);
#pragma unroll
        for (int f = 0; f < 8; f++) {
            int j0 = jb + f * 8;
            float s00 = gridscore(sqr0, acc[f][0], sc[j0]);
            float s01 = gridscore(sqr0, acc[f][1], sc[j0 + 1]);
            float s10 = gridscore(sqr1, acc[f][2], sc[j0]);
            float s11 = gridscore(sqr1, acc[f][3], sc[j0 + 1]);
            bs0 = fminf(bs0, fminf(s00, s01));
            bs1 = fminf(bs1, fminf(s10, s11));
        }
        float q0 = bs0, q1 = bs1;
        q0 = fminf(q0, __shfl_xor_sync(0xFFFFFFFFu, q0, 1));
        q0 = fminf(q0, __shfl_xor_sync(0xFFFFFFFFu, q0, 2));
        q1 = fminf(q1, __shfl_xor_sync(0xFFFFFFFFu, q1, 1));
        q1 = fminf(q1, __shfl_xor_sync(0xFFFFFFFFu, q1, 2));
        const float thr0 = q0 + MARGIN, thr1 = q1 + MARGIN;

        // ---- epilogue sweep 2: push margin candidates ----
#pragma unroll
        for (int f = 0; f < 8; f++) {
            int j0 = jb + f * 8;
            float s00 = gridscore(sqr0, acc[f][0], sc[j0]);
            float s01 = gridscore(sqr0, acc[f][1], sc[j0 + 1]);
            float s10 = gridscore(sqr1, acc[f][2], sc[j0]);
            float s11 = gridscore(sqr1, acc[f][3], sc[j0 + 1]);
            if (s00 <= thr0) { int p = atomicAdd(&cCnt[rb], 1);     if (p < CAND_CAP) cList[rb * CAND_CAP + p] = j0; }
            if (s01 <= thr0) { int p = atomicAdd(&cCnt[rb], 1);     if (p < CAND_CAP) cList[rb * CAND_CAP + p] = j0 + 1; }
            if (s10 <= thr1) { int p = atomicAdd(&cCnt[rb + 8], 1); if (p < CAND_CAP) cList[(rb + 8) * CAND_CAP + p] = j0; }
            if (s11 <= thr1) { int p = atomicAdd(&cCnt[rb + 8], 1); if (p < CAND_CAP) cList[(rb + 8) * CAND_CAP + p] = j0 + 1; }
        }
        __syncthreads();
    }

    // ---- exact rescore of candidates (4 threads per row, proven) ----
    {
        int row = tid >> 2, h = tid & 3;
        int cnt = cCnt[row];
        float bsv = 3.0e38f; int bi = NEMB;
        if (cnt <= CAND_CAP) {
            for (int i = h; i < cnt; i += 4) {
                int j = cList[row * CAND_CAP + i];
                float s = rescore(input, r0 + row, j, sc[j], sSq[row]);
                if (s < bsv || (s == bsv && j < bi)) { bsv = s; bi = j; }
            }
        } else {  // overflow fallback: exact scan of all 512
            for (int j = h; j < NEMB; j += 4) {
                float s = rescore(input, r0 + row, j, sc[j], sSq[row]);
                if (s < bsv || (s == bsv && j < bi)) { bsv = s; bi = j; }
            }
        }
#pragma unroll
        for (int o = 1; o < 4; o <<= 1) {
            float os = __shfl_xor_sync(0xFFFFFFFFu, bsv, o);
            int   oi = __shfl_xor_sync(0xFFFFFFFFu, bi, o);
            if (os < bsv || (os == bsv && oi < bi)) { bsv = os; bi = oi; }
        }
        if (h == 0) {
            sInd[row] = bi;
            ind_out[r0 + row] = (float)bi;
        }
    }
    __syncthreads();   // sInd ready; cList dead -> dred region reusable

    // ---- gather -> out, diff accumulation (proven) ----
    {
        int r = tid >> 2, h = tid & 3;
        int jb2 = sInd[r];
        const float4* qp = reinterpret_cast<const float4*>(g_EN + jb2 * DIMD + h * 64);
        const float4* xp = reinterpret_cast<const float4*>(input + (r0 + r) * DIMD + h * 64);
        float4* op = reinterpret_cast<float4*>(out + (r0 + r) * DIMD + h * 64);
        float fsum = 0.f;
#pragma unroll 8
        for (int k = 0; k < 16; k++) {
            float4 q = qp[k], x = xp[k];
            op[k] = q;
            float dx = q.x - x.x, dy = q.y - x.y, dz = q.z - x.z, dw = q.w - x.w;
            fsum += dx * dx + dy * dy + dz * dz + dw * dw;
        }
        dred[tid] = (double)fsum;
    }
    __syncthreads();
    for (int o = 256; o > 0; o >>= 1) { if (tid < o) dred[tid] += dred[tid + o]; __syncthreads(); }
    if (tid == 0) g_partials[blockIdx.x] = dred[0];
}

// ---------------- final: loss = diff - entropy/E^2 ----------------
__global__ void k_final(float* __restrict__ loss_out, int nblocks, long n) {
    __shared__ double red[256];
    int t = threadIdx.x;
    double s = 0.0;
    for (int i = t; i < nblocks; i += 256) s += g_partials[i];
    red[t] = s; __syncthreads();
    for (int o = 128; o > 0; o >>= 1) { if (t < o) red[t] += red[t + o]; __syncthreads(); }
    if (t == 0) {
        double diff = red[0] / (double)n;
        loss_out[0] = (float)(diff - g_entropy / ((double)NEMB * (double)NEMB));
    }
}

extern "C" void kernel_launch(void* const* d_in, const int* in_sizes, int n_in,
                              void* d_out, int out_size) {
    const float* input = (const float*)d_in[0];
    const float* emb   = (const float*)d_in[1];
    long n     = (long)in_sizes[0];        // 33554432
    int  nrows = (int)(n / DIMD);          // 131072
    int  nblk  = nrows / TM;               // 1024
    float* out    = (float*)d_out;
    float* loss_p = out + n;               // layout: [out | loss | embed_ind]
    float* ind_p  = out + n + 1;

    cudaFuncSetAttribute(k_main, cudaFuncAttributeMaxDynamicSharedMemorySize, SMEM_REQ);
    k_norm   <<<NEMB, 64>>>(emb);
    k_entropy<<<1, 256>>>();
    k_prepB  <<<512, 256>>>();
    k_main   <<<nblk, NTHREADS, SMEM_REQ>>>(input, out, ind_p);
    k_final  <<<1, 256>>>(loss_p, nblk, n);
}

// round 15
// speedup vs baseline: 3.2539x; 2.3765x over previous
#include <cuda_runtime.h>
#include <cuda_bf16.h>
#include <cstdint>

#define DIMD 256
#define NEMB 512
#define TM   128
#define MARGIN 0.25f
#define CAND_CAP 16

__device__ __align__(16) float          g_EN [NEMB * DIMD];  // normalized codebook f32 [j][k]
__device__ __align__(16) float          g_C  [NEMB];         // c_j
__device__ __align__(16) unsigned short g_Bbf[NEMB * DIMD];  // bf16 codebook [j][k]
__device__ double g_entropy;
__device__ double g_partials[2048];

// ---- smem layout (byte offsets) ----
#define A_STRIDE  528u              // 264 halves: bank stride 4 -> ldmatrix conflict-free
#define A_OFF     0u                // 128 * 528 = 67584
#define B_OFF     67584u            // 2 bufs x 67584 = 135168
#define B_BUFSZ   67584u
#define SC_OFF    202752u           // 512 f
#define SSQ_OFF   204800u           // 128 f
#define SIND_OFF  205312u           // 128 i
#define CCNT_OFF  205824u           // 128 i
#define CLIST_OFF 206336u           // 128 * 16 i = 8192
#define DRED_OFF  214528u           // 256 d
#define SMEM_REQ  216576u

#define CP16(dst, src) asm volatile("cp.async.cg.shared.global [%0], [%1], 16;" :: "r"(dst), "l"(src))
#define CP_COMMIT()    asm volatile("cp.async.commit_group;")
#define CP_WAIT(n)     asm volatile("cp.async.wait_group %0;" :: "n"(n))

#define LDM_X4(r0, r1, r2, r3, a) \
    asm volatile("ldmatrix.sync.aligned.m8n8.x4.shared.b16 {%0,%1,%2,%3}, [%4];" \
                 : "=r"(r0), "=r"(r1), "=r"(r2), "=r"(r3) : "r"(a))

#define MMA_BF16(c, a0, a1, a2, a3, b0, b1) \
    asm volatile("mma.sync.aligned.m16n8k16.row.col.f32.bf16.bf16.f32 " \
                 "{%0,%1,%2,%3}, {%4,%5,%6,%7}, {%8,%9}, {%0,%1,%2,%3};" \
                 : "+f"((c)[0]), "+f"((c)[1]), "+f"((c)[2]), "+f"((c)[3]) \
                 : "r"(a0), "r"(a1), "r"(a2), "r"(a3), "r"(b0), "r"(b1))

__device__ __forceinline__ uint32_t bf16x2_of(float lo, float hi) {
    uint32_t r;
    asm("cvt.rn.bf16x2.f32 %0, %1, %2;" : "=r"(r) : "f"(hi), "f"(lo));  // %2 -> low half
    return r;
}
__device__ __forceinline__ float gridscore(float sqr, float dot, float cj) {
    return __fadd_rn(__fsub_rn(sqr, __fmul_rn(2.0f, dot)), cj);
}

// ---------------- Phase A1: normalize codebook rows (proven) ----------------
__global__ void k_norm(const float* __restrict__ emb) {
    int j = blockIdx.x, t = threadIdx.x;  // 512 x 64
    __shared__ float red[64];
    float4 v = reinterpret_cast<const float4*>(emb + j * DIMD)[t];
    red[t] = v.x * v.x + v.y * v.y + v.z * v.z + v.w * v.w;
    __syncthreads();
    for (int o = 32; o > 0; o >>= 1) { if (t < o) red[t] += red[t + o]; __syncthreads(); }
    float nrm = sqrtf(red[0]);
    __syncthreads();
    float4 q;
    q.x = v.x / nrm; q.y = v.y / nrm; q.z = v.z / nrm; q.w = v.w / nrm;
    reinterpret_cast<float4*>(g_EN + j * DIMD)[t] = q;
    red[t] = q.x * q.x + q.y * q.y + q.z * q.z + q.w * q.w;
    __syncthreads();
    for (int o = 32; o > 0; o >>= 1) { if (t < o) red[t] += red[t + o]; __syncthreads(); }
    if (t == 0) g_C[j] = red[0];
}

// ---------------- Phase A2: entropy (proven) ----------------
__global__ void k_entropy() {
    int t = threadIdx.x;  // 256
    float s = 0.f;
    for (int j = 0; j < NEMB; j++) s += g_EN[j * DIMD + t];
    double val = 2.0 * (double)NEMB * ((double)g_C[t] + (double)g_C[t + 256])
               - 2.0 * (double)s * (double)s;
    __shared__ double red[256];
    red[t] = val; __syncthreads();
    for (int o = 128; o > 0; o >>= 1) { if (t < o) red[t] += red[t + o]; __syncthreads(); }
    if (t == 0) g_entropy = red[0];
}

// ---------------- Phase A3: bf16 codebook ----------------
__global__ void k_prepB() {
    int idx = blockIdx.x * 256 + threadIdx.x;   // 131072
    float x = g_EN[idx];
    unsigned short h;
    asm("cvt.rn.bf16.f32 %0, %1;" : "=h"(h) : "f"(x));
    g_Bbf[idx] = h;
}

// exact rescore: serial ascending-k fmaf chain == R2's passing arithmetic
__device__ __forceinline__ float rescore(const float* __restrict__ input, long grow,
                                         int j, float cj, float sqr) {
    const float4* xp = reinterpret_cast<const float4*>(input + grow * DIMD);
    const float4* ep = reinterpret_cast<const float4*>(g_EN + j * DIMD);
    float d = 0.f;
#pragma unroll 8
    for (int k = 0; k < 64; k++) {
        float4 x = xp[k], e = ep[k];
        d = __fmaf_rn(x.x, e.x, d); d = __fmaf_rn(x.y, e.y, d);
        d = __fmaf_rn(x.z, e.z, d); d = __fmaf_rn(x.w, e.w, d);
    }
    return __fadd_rn(__fsub_rn(sqr, __fmul_rn(2.0f, d)), cj);
}

// ------ Main: R7 exactly, with B-fragment register-ring pipelining only -----
__global__ void __launch_bounds__(256, 1) k_main(
        const float* __restrict__ input,
        float* __restrict__ out,
        float* __restrict__ ind_out)
{
    extern __shared__ char smraw[];
    uint32_t raw32 = (uint32_t)__cvta_generic_to_shared(smraw);
    float*  sc    = (float*)(smraw + SC_OFF);
    float*  sSq   = (float*)(smraw + SSQ_OFF);
    int*    sInd  = (int*)(smraw + SIND_OFF);
    int*    cCnt  = (int*)(smraw + CCNT_OFF);
    int*    cList = (int*)(smraw + CLIST_OFF);
    double* dred  = (double*)(smraw + DRED_OFF);

    const int  tid  = threadIdx.x;
    const int  wid  = tid >> 5, lane = tid & 31;
    const long r0   = (long)blockIdx.x * TM;
    const int  tq   = lane >> 3, rr = lane & 7;

    if (tid < TM) cCnt[tid] = 0;
    for (int i = tid; i < NEMB; i += 256) sc[i] = g_C[i];

    // ---- A load: f32 -> bf16 into padded smem; exact double row norms ----
    {
        int r = tid >> 1, h = tid & 1;
        const float4* src = reinterpret_cast<const float4*>(input + (r0 + r) * DIMD + h * 128);
        uint32_t dst = raw32 + A_OFF + (uint32_t)r * A_STRIDE + (uint32_t)h * 256u;
        double dsq = 0.0;
#pragma unroll 8
        for (int q = 0; q < 32; q++) {
            float4 v = src[q];
            dsq += (double)v.x * v.x + (double)v.y * v.y + (double)v.z * v.z + (double)v.w * v.w;
            uint32_t p0 = bf16x2_of(v.x, v.y);
            uint32_t p1 = bf16x2_of(v.z, v.w);
            asm volatile("st.shared.v2.b32 [%0], {%1, %2};" :: "r"(dst + q * 8u), "r"(p0), "r"(p1));
        }
        dred[tid] = dsq;
    }
    // prefetch B chunk 0
    {
#pragma unroll
        for (int q = 0; q < 16; q++) {
            int idx = tid + q * 256;
            int row = idx >> 5, seg = idx & 31;
            CP16(raw32 + B_OFF + (uint32_t)row * A_STRIDE + (uint32_t)seg * 16u,
                 (const char*)g_Bbf + (size_t)row * 512 + seg * 16);
        }
        CP_COMMIT();
    }
    __syncthreads();
    if (tid < TM) sSq[tid] = (float)(dred[2 * tid] + dred[2 * tid + 1]);
    __syncthreads();

    // ---- fragment addresses (R7's proven lane patterns) ----
    const uint32_t aAddrBase = raw32 + A_OFF
        + (uint32_t)(wid * 16 + ((tq & 1) << 3) + rr) * A_STRIDE
        + (uint32_t)(((tq >> 1) << 3) * 2);
    const uint32_t bLanePart = (uint32_t)(((tq >> 1) * 8 + rr) * A_STRIDE + ((tq & 1) << 3) * 2);

    const float sqrA = sSq[wid * 16 + (lane >> 2)];
    const float sqrB = sSq[wid * 16 + (lane >> 2) + 8];
    const int   rAl  = wid * 16 + (lane >> 2);
    const int   rBl  = rAl + 8;
    float bsA = 3.0e38f, bsB = 3.0e38f;

    for (int ch = 0; ch < 4; ch++) {
        // prefetch next chunk into other buffer
        if (ch < 3) {
#pragma unroll
            for (int q = 0; q < 16; q++) {
                int idx = tid + q * 256;
                int row = idx >> 5, seg = idx & 31;
                CP16(raw32 + B_OFF + (uint32_t)((ch + 1) & 1) * B_BUFSZ
                         + (uint32_t)row * A_STRIDE + (uint32_t)seg * 16u,
                     (const char*)g_Bbf + (size_t)((ch + 1) * 128 + row) * 512 + seg * 16);
            }
            CP_COMMIT();
            CP_WAIT(1);
        } else {
            CP_WAIT(0);
        }
        __syncthreads();

        const uint32_t bBuf = raw32 + B_OFF + (uint32_t)(ch & 1) * B_BUFSZ + bLanePart;
        float acc[16][4];
#pragma unroll
        for (int i = 0; i < 16; i++)
            acc[i][0] = acc[i][1] = acc[i][2] = acc[i][3] = 0.f;

        // ---- register-ring pipelined mainloop (only change vs R7) ----
        uint32_t af[2][4], bfr[2][4];
        LDM_X4(af[0][0], af[0][1], af[0][2], af[0][3], aAddrBase);
        LDM_X4(bfr[0][0], bfr[0][1], bfr[0][2], bfr[0][3], bBuf);
#pragma unroll
        for (int kk = 0; kk < 16; kk++) {
            const int ca = kk & 1;
#pragma unroll
            for (int ntp = 0; ntp < 8; ntp++) {
                const int cb = ntp & 1;
                if (ntp < 7) {
                    LDM_X4(bfr[cb ^ 1][0], bfr[cb ^ 1][1], bfr[cb ^ 1][2], bfr[cb ^ 1][3],
                           bBuf + (uint32_t)(ntp + 1) * (16u * A_STRIDE) + (uint32_t)kk * 32u);
                } else if (kk < 15) {
                    LDM_X4(af[ca ^ 1][0], af[ca ^ 1][1], af[ca ^ 1][2], af[ca ^ 1][3],
                           aAddrBase + (uint32_t)(kk + 1) * 32u);
                    LDM_X4(bfr[cb ^ 1][0], bfr[cb ^ 1][1], bfr[cb ^ 1][2], bfr[cb ^ 1][3],
                           bBuf + (uint32_t)(kk + 1) * 32u);
                }
                MMA_BF16(acc[ntp * 2],
                         af[ca][0], af[ca][1], af[ca][2], af[ca][3],
                         bfr[cb][0], bfr[cb][1]);
                MMA_BF16(acc[ntp * 2 + 1],
                         af[ca][0], af[ca][1], af[ca][2], af[ca][3],
                         bfr[cb][2], bfr[cb][3]);
            }
        }

        // ---- epilogue sweep 1: fold into running per-row best (R7 verbatim) --
        const int jbase = ch * 128 + 2 * (lane & 3);
#pragma unroll
        for (int nt = 0; nt < 16; nt++) {
            int j0 = jbase + nt * 8;
            float sA0 = gridscore(sqrA, acc[nt][0], sc[j0]);
            float sA1 = gridscore(sqrA, acc[nt][1], sc[j0 + 1]);
            float sB0 = gridscore(sqrB, acc[nt][2], sc[j0]);
            float sB1 = gridscore(sqrB, acc[nt][3], sc[j0 + 1]);
            bsA = fminf(bsA, fminf(sA0, sA1));
            bsB = fminf(bsB, fminf(sB0, sB1));
        }
        float qA = bsA, qB = bsB;
        qA = fminf(qA, __shfl_xor_sync(0xFFFFFFFFu, qA, 1));
        qA = fminf(qA, __shfl_xor_sync(0xFFFFFFFFu, qA, 2));
        qB = fminf(qB, __shfl_xor_sync(0xFFFFFFFFu, qB, 1));
        qB = fminf(qB, __shfl_xor_sync(0xFFFFFFFFu, qB, 2));
        const float thrA = qA + MARGIN, thrB = qB + MARGIN;

        // ---- epilogue sweep 2: push margin candidates (R7 verbatim) ----
#pragma unroll
        for (int nt = 0; nt < 16; nt++) {
            int j0 = jbase + nt * 8;
            float sA0 = gridscore(sqrA, acc[nt][0], sc[j0]);
            float sA1 = gridscore(sqrA, acc[nt][1], sc[j0 + 1]);
            float sB0 = gridscore(sqrB, acc[nt][2], sc[j0]);
            float sB1 = gridscore(sqrB, acc[nt][3], sc[j0 + 1]);
            if (sA0 <= thrA) { int p = atomicAdd(&cCnt[rAl], 1); if (p < CAND_CAP) cList[rAl * CAND_CAP + p] = j0; }
            if (sA1 <= thrA) { int p = atomicAdd(&cCnt[rAl], 1); if (p < CAND_CAP) cList[rAl * CAND_CAP + p] = j0 + 1; }
            if (sB0 <= thrB) { int p = atomicAdd(&cCnt[rBl], 1); if (p < CAND_CAP) cList[rBl * CAND_CAP + p] = j0; }
            if (sB1 <= thrB) { int p = atomicAdd(&cCnt[rBl], 1); if (p < CAND_CAP) cList[rBl * CAND_CAP + p] = j0 + 1; }
        }
        __syncthreads();
    }

    // ---- exact rescore of candidates (2 threads per row, proven) ----
    {
        int row = tid >> 1, h = tid & 1;
        int cnt = cCnt[row];
        float bsv = 3.0e38f; int bi = NEMB;
        if (cnt <= CAND_CAP) {
            for (int i = h; i < cnt; i += 2) {
                int j = cList[row * CAND_CAP + i];
                float s = rescore(input, r0 + row, j, sc[j], sSq[row]);
                if (s < bsv || (s == bsv && j < bi)) { bsv = s; bi = j; }
            }
        } else {  // overflow fallback: exact scan of all 512
            for (int j = h; j < NEMB; j += 2) {
                float s = rescore(input, r0 + row, j, sc[j], sSq[row]);
                if (s < bsv || (s == bsv && j < bi)) { bsv = s; bi = j; }
            }
        }
        float os = __shfl_xor_sync(0xFFFFFFFFu, bsv, 1);
        int   oi = __shfl_xor_sync(0xFFFFFFFFu, bi, 1);
        if (os < bsv || (os == bsv && oi < bi)) { bsv = os; bi = oi; }
        if (h == 0) {
            sInd[row] = bi;
            ind_out[r0 + row] = (float)bi;
        }
    }
    __syncthreads();

    // ---- gather -> out, diff accumulation (proven) ----
    {
        int r = tid >> 1, h = tid & 1;
        int jb2 = sInd[r];
        const float4* qp = reinterpret_cast<const float4*>(g_EN + jb2 * DIMD + h * 128);
        const float4* xp = reinterpret_cast<const float4*>(input + (r0 + r) * DIMD + h * 128);
        float4* op = reinterpret_cast<float4*>(out + (r0 + r) * DIMD + h * 128);
        float fsum = 0.f;
#pragma unroll 8
        for (int k = 0; k < 32; k++) {
            float4 q = qp[k], x = xp[k];
            op[k] = q;
            float dx = q.x - x.x, dy = q.y - x.y, dz = q.z - x.z, dw = q.w - x.w;
            fsum += dx * dx + dy * dy + dz * dz + dw * dw;
        }
        dred[tid] = (double)fsum;
    }
    __syncthreads();
    for (int o = 128; o > 0; o >>= 1) { if (tid < o) dred[tid] += dred[tid + o]; __syncthreads(); }
    if (tid == 0) g_partials[blockIdx.x] = dred[0];
}

// ---------------- final: loss = diff - entropy/E^2 ----------------
__global__ void k_final(float* __restrict__ loss_out, int nblocks, long n) {
    __shared__ double red[256];
    int t = threadIdx.x;
    double s = 0.0;
    for (int i = t; i < nblocks; i += 256) s += g_partials[i];
    red[t] = s; __syncthreads();
    for (int o = 128; o > 0; o >>= 1) { if (t < o) red[t] += red[t + o]; __syncthreads(); }
    if (t == 0) {
        double diff = red[0] / (double)n;
        loss_out[0] = (float)(diff - g_entropy / ((double)NEMB * (double)NEMB));
    }
}

extern "C" void kernel_launch(void* const* d_in, const int* in_sizes, int n_in,
                              void* d_out, int out_size) {
    const float* input = (const float*)d_in[0];
    const float* emb   = (const float*)d_in[1];
    long n     = (long)in_sizes[0];        // 33554432
    int  nrows = (int)(n / DIMD);          // 131072
    int  nblk  = nrows / TM;               // 1024
    float* out    = (float*)d_out;
    float* loss_p = out + n;               // layout: [out | loss | embed_ind]
    float* ind_p  = out + n + 1;

    cudaFuncSetAttribute(k_main, cudaFuncAttributeMaxDynamicSharedMemorySize, SMEM_REQ);
    k_norm   <<<NEMB, 64>>>(emb);
    k_entropy<<<1, 256>>>();
    k_prepB  <<<512, 256>>>();
    k_main   <<<nblk, 256, SMEM_REQ>>>(input, out, ind_p);
    k_final  <<<1, 256>>>(loss_p, nblk, n);
}

// round 16
// speedup vs baseline: 3.3191x; 1.0200x over previous
#include <cuda_runtime.h>
#include <cuda_bf16.h>
#include <cstdint>

#define DIMD 256
#define NEMB 512
#define TM   128
#define MARGIN 0.25f
#define CAND_CAP 16

__device__ __align__(16) float          g_EN [NEMB * DIMD];  // normalized codebook f32 [j][k]
__device__ __align__(16) float          g_C  [NEMB];         // c_j
__device__ __align__(16) unsigned short g_Bbf[NEMB * DIMD];  // bf16 codebook [j][k]
__device__ double g_entropy;
__device__ double g_partials[2048];

// ---- smem layout (byte offsets) ----
#define A_STRIDE  528u              // 264 halves: bank stride 4 -> ldmatrix conflict-free
#define A_OFF     0u                // 128 * 528 = 67584
#define B_OFF     67584u            // 2 bufs x 67584 = 135168
#define B_BUFSZ   67584u
#define SC_OFF    202752u           // 512 f
#define SSQ_OFF   204800u           // 128 f
#define SIND_OFF  205312u           // 128 i
#define CCNT_OFF  205824u           // 128 i
#define CLIST_OFF 206336u           // 128 * 16 i = 8192
#define DRED_OFF  214528u           // 256 d
#define SMEM_REQ  216576u

#define CP16(dst, src) asm volatile("cp.async.cg.shared.global [%0], [%1], 16;" :: "r"(dst), "l"(src))
#define CP_COMMIT()    asm volatile("cp.async.commit_group;")
#define CP_WAIT(n)     asm volatile("cp.async.wait_group %0;" :: "n"(n))

#define LDM_X4(r0, r1, r2, r3, a) \
    asm volatile("ldmatrix.sync.aligned.m8n8.x4.shared.b16 {%0,%1,%2,%3}, [%4];" \
                 : "=r"(r0), "=r"(r1), "=r"(r2), "=r"(r3) : "r"(a))

#define MMA_BF16(c, a0, a1, a2, a3, b0, b1) \
    asm volatile("mma.sync.aligned.m16n8k16.row.col.f32.bf16.bf16.f32 " \
                 "{%0,%1,%2,%3}, {%4,%5,%6,%7}, {%8,%9}, {%0,%1,%2,%3};" \
                 : "+f"((c)[0]), "+f"((c)[1]), "+f"((c)[2]), "+f"((c)[3]) \
                 : "r"(a0), "r"(a1), "r"(a2), "r"(a3), "r"(b0), "r"(b1))

__device__ __forceinline__ uint32_t bf16x2_of(float lo, float hi) {
    uint32_t r;
    asm("cvt.rn.bf16x2.f32 %0, %1, %2;" : "=r"(r) : "f"(hi), "f"(lo));  // %2 -> low half
    return r;
}
__device__ __forceinline__ float gridscore(float sqr, float dot, float cj) {
    return __fadd_rn(__fsub_rn(sqr, __fmul_rn(2.0f, dot)), cj);
}

// ---------------- Phase A1: normalize codebook rows (proven) ----------------
__global__ void k_norm(const float* __restrict__ emb) {
    int j = blockIdx.x, t = threadIdx.x;  // 512 x 64
    __shared__ float red[64];
    float4 v = reinterpret_cast<const float4*>(emb + j * DIMD)[t];
    red[t] = v.x * v.x + v.y * v.y + v.z * v.z + v.w * v.w;
    __syncthreads();
    for (int o = 32; o > 0; o >>= 1) { if (t < o) red[t] += red[t + o]; __syncthreads(); }
    float nrm = sqrtf(red[0]);
    __syncthreads();
    float4 q;
    q.x = v.x / nrm; q.y = v.y / nrm; q.z = v.z / nrm; q.w = v.w / nrm;
    reinterpret_cast<float4*>(g_EN + j * DIMD)[t] = q;
    red[t] = q.x * q.x + q.y * q.y + q.z * q.z + q.w * q.w;
    __syncthreads();
    for (int o = 32; o > 0; o >>= 1) { if (t < o) red[t] += red[t + o]; __syncthreads(); }
    if (t == 0) g_C[j] = red[0];
}

// ---------------- Phase A2: entropy (proven) ----------------
__global__ void k_entropy() {
    int t = threadIdx.x;  // 256
    float s = 0.f;
    for (int j = 0; j < NEMB; j++) s += g_EN[j * DIMD + t];
    double val = 2.0 * (double)NEMB * ((double)g_C[t] + (double)g_C[t + 256])
               - 2.0 * (double)s * (double)s;
    __shared__ double red[256];
    red[t] = val; __syncthreads();
    for (int o = 128; o > 0; o >>= 1) { if (t < o) red[t] += red[t + o]; __syncthreads(); }
    if (t == 0) g_entropy = red[0];
}

// ---------------- Phase A3: bf16 codebook ----------------
__global__ void k_prepB() {
    int idx = blockIdx.x * 256 + threadIdx.x;   // 131072
    float x = g_EN[idx];
    unsigned short h;
    asm("cvt.rn.bf16.f32 %0, %1;" : "=h"(h) : "f"(x));
    g_Bbf[idx] = h;
}

// exact rescore: serial ascending-k fmaf chain == R2's passing arithmetic
__device__ __forceinline__ float rescore(const float* __restrict__ input, long grow,
                                         int j, float cj, float sqr) {
    const float4* xp = reinterpret_cast<const float4*>(input + grow * DIMD);
    const float4* ep = reinterpret_cast<const float4*>(g_EN + j * DIMD);
    float d = 0.f;
#pragma unroll 8
    for (int k = 0; k < 64; k++) {
        float4 x = xp[k], e = ep[k];
        d = __fmaf_rn(x.x, e.x, d); d = __fmaf_rn(x.y, e.y, d);
        d = __fmaf_rn(x.z, e.z, d); d = __fmaf_rn(x.w, e.w, d);
    }
    return __fadd_rn(__fsub_rn(sqr, __fmul_rn(2.0f, d)), cj);
}

// ----- Main: R7 structure; merged single-pass epilogue (scores in regs) -----
__global__ void __launch_bounds__(256, 1) k_main(
        const float* __restrict__ input,
        float* __restrict__ out,
        float* __restrict__ ind_out)
{
    extern __shared__ char smraw[];
    uint32_t raw32 = (uint32_t)__cvta_generic_to_shared(smraw);
    float*  sc    = (float*)(smraw + SC_OFF);
    float*  sSq   = (float*)(smraw + SSQ_OFF);
    int*    sInd  = (int*)(smraw + SIND_OFF);
    int*    cCnt  = (int*)(smraw + CCNT_OFF);
    int*    cList = (int*)(smraw + CLIST_OFF);
    double* dred  = (double*)(smraw + DRED_OFF);

    const int  tid  = threadIdx.x;
    const int  wid  = tid >> 5, lane = tid & 31;
    const long r0   = (long)blockIdx.x * TM;
    const int  tq   = lane >> 3, rr = lane & 7;

    if (tid < TM) cCnt[tid] = 0;
    for (int i = tid; i < NEMB; i += 256) sc[i] = g_C[i];

    // ---- A load: f32 -> bf16 into padded smem; exact double row norms ----
    {
        int r = tid >> 1, h = tid & 1;
        const float4* src = reinterpret_cast<const float4*>(input + (r0 + r) * DIMD + h * 128);
        uint32_t dst = raw32 + A_OFF + (uint32_t)r * A_STRIDE + (uint32_t)h * 256u;
        double dsq = 0.0;
#pragma unroll 8
        for (int q = 0; q < 32; q++) {
            float4 v = src[q];
            dsq += (double)v.x * v.x + (double)v.y * v.y + (double)v.z * v.z + (double)v.w * v.w;
            uint32_t p0 = bf16x2_of(v.x, v.y);
            uint32_t p1 = bf16x2_of(v.z, v.w);
            asm volatile("st.shared.v2.b32 [%0], {%1, %2};" :: "r"(dst + q * 8u), "r"(p0), "r"(p1));
        }
        dred[tid] = dsq;
    }
    // prefetch B chunk 0
    {
#pragma unroll
        for (int q = 0; q < 16; q++) {
            int idx = tid + q * 256;
            int row = idx >> 5, seg = idx & 31;
            CP16(raw32 + B_OFF + (uint32_t)row * A_STRIDE + (uint32_t)seg * 16u,
                 (const char*)g_Bbf + (size_t)row * 512 + seg * 16);
        }
        CP_COMMIT();
    }
    __syncthreads();
    if (tid < TM) sSq[tid] = (float)(dred[2 * tid] + dred[2 * tid + 1]);
    __syncthreads();

    // ---- fragment addresses (R7's proven lane patterns) ----
    const uint32_t aAddrBase = raw32 + A_OFF
        + (uint32_t)(wid * 16 + ((tq & 1) << 3) + rr) * A_STRIDE
        + (uint32_t)(((tq >> 1) << 3) * 2);
    const uint32_t bLanePart = (uint32_t)(((tq >> 1) * 8 + rr) * A_STRIDE + ((tq & 1) << 3) * 2);

    const float sqrA = sSq[wid * 16 + (lane >> 2)];
    const float sqrB = sSq[wid * 16 + (lane >> 2) + 8];
    const int   rAl  = wid * 16 + (lane >> 2);
    const int   rBl  = rAl + 8;
    float bsA = 3.0e38f, bsB = 3.0e38f;

    for (int ch = 0; ch < 4; ch++) {
        // prefetch next chunk into other buffer
        if (ch < 3) {
#pragma unroll
            for (int q = 0; q < 16; q++) {
                int idx = tid + q * 256;
                int row = idx >> 5, seg = idx & 31;
                CP16(raw32 + B_OFF + (uint32_t)((ch + 1) & 1) * B_BUFSZ
                         + (uint32_t)row * A_STRIDE + (uint32_t)seg * 16u,
                     (const char*)g_Bbf + (size_t)((ch + 1) * 128 + row) * 512 + seg * 16);
            }
            CP_COMMIT();
            CP_WAIT(1);
        } else {
            CP_WAIT(0);
        }
        __syncthreads();

        const uint32_t bBuf = raw32 + B_OFF + (uint32_t)(ch & 1) * B_BUFSZ + bLanePart;
        float acc[16][4];
#pragma unroll
        for (int i = 0; i < 16; i++)
            acc[i][0] = acc[i][1] = acc[i][2] = acc[i][3] = 0.f;

#pragma unroll 2
        for (int kk = 0; kk < 16; kk++) {
            uint32_t a0, a1, a2, a3;
            LDM_X4(a0, a1, a2, a3, aAddrBase + (uint32_t)kk * 32u);
#pragma unroll
            for (int ntp = 0; ntp < 8; ntp++) {
                uint32_t b0, b1, b2, b3;
                LDM_X4(b0, b1, b2, b3, bBuf + (uint32_t)ntp * (16u * A_STRIDE) + (uint32_t)kk * 32u);
                MMA_BF16(acc[ntp * 2],     a0, a1, a2, a3, b0, b1);
                MMA_BF16(acc[ntp * 2 + 1], a0, a1, a2, a3, b2, b3);
            }
        }

        // ---- merged epilogue: scores computed ONCE into acc regs ----
        const int jbase = ch * 128 + 2 * (lane & 3);
#pragma unroll
        for (int nt = 0; nt < 16; nt++) {
            int j0 = jbase + nt * 8;
            float2 cj = *reinterpret_cast<const float2*>(&sc[j0]);   // one LDS.64
            float sA0 = gridscore(sqrA, acc[nt][0], cj.x);
            float sA1 = gridscore(sqrA, acc[nt][1], cj.y);
            float sB0 = gridscore(sqrB, acc[nt][2], cj.x);
            float sB1 = gridscore(sqrB, acc[nt][3], cj.y);
            acc[nt][0] = sA0; acc[nt][1] = sA1;                      // overwrite dots with scores
            acc[nt][2] = sB0; acc[nt][3] = sB1;
            bsA = fminf(bsA, fminf(sA0, sA1));
            bsB = fminf(bsB, fminf(sB0, sB1));
        }
        float qA = bsA, qB = bsB;
        qA = fminf(qA, __shfl_xor_sync(0xFFFFFFFFu, qA, 1));
        qA = fminf(qA, __shfl_xor_sync(0xFFFFFFFFu, qA, 2));
        qB = fminf(qB, __shfl_xor_sync(0xFFFFFFFFu, qB, 1));
        qB = fminf(qB, __shfl_xor_sync(0xFFFFFFFFu, qB, 2));
        const float thrA = qA + MARGIN, thrB = qB + MARGIN;

        // candidate push straight from register scores (no recompute, no LDS)
#pragma unroll
        for (int nt = 0; nt < 16; nt++) {
            int j0 = jbase + nt * 8;
            if (acc[nt][0] <= thrA) { int p = atomicAdd(&cCnt[rAl], 1); if (p < CAND_CAP) cList[rAl * CAND_CAP + p] = j0; }
            if (acc[nt][1] <= thrA) { int p = atomicAdd(&cCnt[rAl], 1); if (p < CAND_CAP) cList[rAl * CAND_CAP + p] = j0 + 1; }
            if (acc[nt][2] <= thrB) { int p = atomicAdd(&cCnt[rBl], 1); if (p < CAND_CAP) cList[rBl * CAND_CAP + p] = j0; }
            if (acc[nt][3] <= thrB) { int p = atomicAdd(&cCnt[rBl], 1); if (p < CAND_CAP) cList[rBl * CAND_CAP + p] = j0 + 1; }
        }
        __syncthreads();
    }

    // ---- exact rescore of candidates (2 threads per row, proven) ----
    {
        int row = tid >> 1, h = tid & 1;
        int cnt = cCnt[row];
        float bsv = 3.0e38f; int bi = NEMB;
        if (cnt <= CAND_CAP) {
            for (int i = h; i < cnt; i += 2) {
                int j = cList[row * CAND_CAP + i];
                float s = rescore(input, r0 + row, j, sc[j], sSq[row]);
                if (s < bsv || (s == bsv && j < bi)) { bsv = s; bi = j; }
            }
        } else {  // overflow fallback: exact scan of all 512
            for (int j = h; j < NEMB; j += 2) {
                float s = rescore(input, r0 + row, j, sc[j], sSq[row]);
                if (s < bsv || (s == bsv && j < bi)) { bsv = s; bi = j; }
            }
        }
        float os = __shfl_xor_sync(0xFFFFFFFFu, bsv, 1);
        int   oi = __shfl_xor_sync(0xFFFFFFFFu, bi, 1);
        if (os < bsv || (os == bsv && oi < bi)) { bsv = os; bi = oi; }
        if (h == 0) {
            sInd[row] = bi;
            ind_out[r0 + row] = (float)bi;
        }
    }
    __syncthreads();

    // ---- gather -> out, diff accumulation (proven) ----
    {
        int r = tid >> 1, h = tid & 1;
        int jb2 = sInd[r];
        const float4* qp = reinterpret_cast<const float4*>(g_EN + jb2 * DIMD + h * 128);
        const float4* xp = reinterpret_cast<const float4*>(input + (r0 + r) * DIMD + h * 128);
        float4* op = reinterpret_cast<float4*>(out + (r0 + r) * DIMD + h * 128);
        float fsum = 0.f;
#pragma unroll 8
        for (int k = 0; k < 32; k++) {
            float4 q = qp[k], x = xp[k];
            op[k] = q;
            float dx = q.x - x.x, dy = q.y - x.y, dz = q.z - x.z, dw = q.w - x.w;
            fsum += dx * dx + dy * dy + dz * dz + dw * dw;
        }
        dred[tid] = (double)fsum;
    }
    __syncthreads();
    for (int o = 128; o > 0; o >>= 1) { if (tid < o) dred[tid] += dred[tid + o]; __syncthreads(); }
    if (tid == 0) g_partials[blockIdx.x] = dred[0];
}

// ---------------- final: loss = diff - entropy/E^2 ----------------
__global__ void k_final(float* __restrict__ loss_out, int nblocks, long n) {
    __shared__ double red[256];
    int t = threadIdx.x;
    double s = 0.0;
    for (int i = t; i < nblocks; i += 256) s += g_partials[i];
    red[t] = s; __syncthreads();
    for (int o = 128; o > 0; o >>= 1) { if (t < o) red[t] += red[t + o]; __syncthreads(); }
    if (t == 0) {
        double diff = red[0] / (double)n;
        loss_out[0] = (float)(diff - g_entropy / ((double)NEMB * (double)NEMB));
    }
}

extern "C" void kernel_launch(void* const* d_in, const int* in_sizes, int n_in,
                              void* d_out, int out_size) {
    const float* input = (const float*)d_in[0];
    const float* emb   = (const float*)d_in[1];
    long n     = (long)in_sizes[0];        // 33554432
    int  nrows = (int)(n / DIMD);          // 131072
    int  nblk  = nrows / TM;               // 1024
    float* out    = (float*)d_out;
    float* loss_p = out + n;               // layout: [out | loss | embed_ind]
    float* ind_p  = out + n + 1;

    cudaFuncSetAttribute(k_main, cudaFuncAttributeMaxDynamicSharedMemorySize, SMEM_REQ);
    k_norm   <<<NEMB, 64>>>(emb);
    k_entropy<<<1, 256>>>();
    k_prepB  <<<512, 256>>>();
    k_main   <<<nblk, 256, SMEM_REQ>>>(input, out, ind_p);
    k_final  <<<1, 256>>>(loss_p, nblk, n);
}